// round 16
// baseline (speedup 1.0000x reference)
#include <cuda_runtime.h>

// Problem constants
#define B_ 4
#define N_ 1024
#define H_ 64
#define D_ 64
#define FE_ 16
#define TOT (B_ * N_)
#define NPROD 64       // producer blocks (bids 0..63)
#define ZSLOTS 128     // output-GEMM slots (claimed by last 128 finishers)
#define ZROWS 32       // rows per zout slot

// Scratch (allocation-free __device__ globals)
__device__ float g_si[TOT];
__device__ float g_sj[TOT];
__device__ float g_rowsum[TOT];
// Monotonic counters — NEVER reset (generation = ticket/4096, replay-safe).
__device__ unsigned g_prod  = 0;
__device__ unsigned g_tick  = 0;
__device__ unsigned g_rdone = 0;

// ---- fence-free coherence primitives ----
__device__ __forceinline__ float ldcg(const float* p) {
    float v;
    asm volatile("ld.global.cg.f32 %0, [%1];" : "=f"(v) : "l"(p));
    return v;
}
__device__ __forceinline__ void stcg(float* p, float v) {
    asm volatile("st.global.cg.f32 [%0], %1;" :: "l"(p), "f"(v));
}
__device__ __forceinline__ void release_inc(unsigned* p) {
    asm volatile("red.release.gpu.global.add.u32 [%0], 1;" :: "l"(p));
}
__device__ __forceinline__ unsigned ld_acquire(const unsigned* p) {
    unsigned v;
    asm volatile("ld.acquire.gpu.global.u32 %0, [%1];" : "=r"(v) : "l"(p));
    return v;
}
__device__ __forceinline__ void spin_until_ge(const unsigned* p, unsigned target,
                                              unsigned max_ns) {
    unsigned ns = 32;
    for (unsigned i = 0; i < (1u << 20); ++i) {
        if ((int)(ld_acquire(p) - target) >= 0) return;
        __nanosleep(ns);
        if (ns < max_ns) ns <<= 1;
    }
}

union SMem {
    struct { float wfs[H_ * D_]; float u1[H_]; float u2[H_]; } p;            // 16.5 KB
    struct { float sev[N_]; float red[8]; } s;                               //  4.1 KB
    struct { float wT[H_ * 65]; float h0s[ZROWS * H_]; float red[16]; float tot; } z; // ~25 KB
};

// ---------------------------------------------------------------------------
// ONE fused kernel, grid 4096 x 256. launch_bounds(256,6) -> reg budget 42
// (R15's (256) let the scheduler pack 8 blocks/SM, capping regs at 32 and
// collapsing per-thread load MLP to ~1-2 -> 47% DRAM). Stream loop is now a
// hand-pipelined 4-deep batch of independent LDG.128s.
// ---------------------------------------------------------------------------
__global__ void __launch_bounds__(256, 6) k_all(const float* __restrict__ h0,
                                                const float* __restrict__ e,
                                                const float* __restrict__ w_fc,
                                                const float* __restrict__ w_attn,
                                                float* __restrict__ out) {
    __shared__ SMem sm;
    __shared__ unsigned sh_ticket;

    const int t = threadIdx.x;
    const int bid = blockIdx.x;
    const int lane = t & 31;
    const int w = t >> 5;

    // ========================= producer (bid < 64) ==========================
    if (bid < NPROD) {
        const float4* w4 = reinterpret_cast<const float4*>(w_fc);
        float4* ws4 = reinterpret_cast<float4*>(sm.p.wfs);
#pragma unroll
        for (int k = t; k < (H_ * D_) / 4; k += 256) ws4[k] = w4[k];
        __syncthreads();

        if (t < 128) {                      // u[h] = sum_d wfs[d*64+h]*a[d]
            const int h = t & 63;
            const float* a = w_attn + (t >> 6) * D_;
            const float* col = sm.p.wfs + h;
            float acc = 0.f;
#pragma unroll
            for (int d = 0; d < D_; ++d)
                acc = fmaf(col[d * H_], __ldg(&a[d]), acc);
            if (t < 64) sm.p.u1[h] = acc; else sm.p.u2[h] = acc;
        }
        __syncthreads();

        const int g = t >> 4, q = t & 15;   // 16 groups x 16 threads
        const float4 w1 = reinterpret_cast<const float4*>(sm.p.u1)[q];
        const float4 w2 = reinterpret_cast<const float4*>(sm.p.u2)[q];
#pragma unroll
        for (int pass = 0; pass < 4; ++pass) {
            const int row = bid * 64 + pass * 16 + g;
            const float4 hv = __ldg(&reinterpret_cast<const float4*>(h0)[row * 16 + q]);
            float s1 = hv.x * w1.x, s2 = hv.x * w2.x;
            s1 = fmaf(hv.y, w1.y, s1); s2 = fmaf(hv.y, w2.y, s2);
            s1 = fmaf(hv.z, w1.z, s1); s2 = fmaf(hv.z, w2.z, s2);
            s1 = fmaf(hv.w, w1.w, s1); s2 = fmaf(hv.w, w2.w, s2);
#pragma unroll
            for (int o = 8; o; o >>= 1) {
                s1 += __shfl_down_sync(0xffffffffu, s1, o, 16);
                s2 += __shfl_down_sync(0xffffffffu, s2, o, 16);
            }
            if (q == 0) { stcg(&g_sj[row], s1); stcg(&g_si[row], s2); }
        }
        __syncthreads();                    // peers' stcg ordered before release
        if (t == 0) release_inc(&g_prod);
        __syncthreads();                    // before smem is repurposed
    }

    // ============= stream phase: hand-pipelined, MLP >= 4/thread ============
    {
        const int fg = (lane & 3) * 4;
        const float af0 = __ldg(&w_attn[2 * D_ + fg + 0]);
        const float af1 = __ldg(&w_attn[2 * D_ + fg + 1]);
        const float af2 = __ldg(&w_attn[2 * D_ + fg + 2]);
        const float af3 = __ldg(&w_attn[2 * D_ + fg + 3]);
        const float4* e4 = reinterpret_cast<const float4*>(e) + (size_t)bid * (N_ * 4);

#pragma unroll
        for (int g4 = 0; g4 < 4; ++g4) {
            const int i0 = t + (g4 * 4 + 0) * 256;
            // 4 independent loads issued back-to-back (no consumer between)
            const float4 v0 = __ldcs(&e4[i0 + 0 * 256]);
            const float4 v1 = __ldcs(&e4[i0 + 1 * 256]);
            const float4 v2 = __ldcs(&e4[i0 + 2 * 256]);
            const float4 v3 = __ldcs(&e4[i0 + 3 * 256]);

            float p0 = v0.x * af0; p0 = fmaf(v0.y, af1, p0); p0 = fmaf(v0.z, af2, p0); p0 = fmaf(v0.w, af3, p0);
            float p1 = v1.x * af0; p1 = fmaf(v1.y, af1, p1); p1 = fmaf(v1.z, af2, p1); p1 = fmaf(v1.w, af3, p1);
            float p2 = v2.x * af0; p2 = fmaf(v2.y, af1, p2); p2 = fmaf(v2.z, af2, p2); p2 = fmaf(v2.w, af3, p2);
            float p3 = v3.x * af0; p3 = fmaf(v3.y, af1, p3); p3 = fmaf(v3.z, af2, p3); p3 = fmaf(v3.w, af3, p3);

            p0 += __shfl_xor_sync(0xffffffffu, p0, 1); p0 += __shfl_xor_sync(0xffffffffu, p0, 2);
            p1 += __shfl_xor_sync(0xffffffffu, p1, 1); p1 += __shfl_xor_sync(0xffffffffu, p1, 2);
            p2 += __shfl_xor_sync(0xffffffffu, p2, 1); p2 += __shfl_xor_sync(0xffffffffu, p2, 2);
            p3 += __shfl_xor_sync(0xffffffffu, p3, 1); p3 += __shfl_xor_sync(0xffffffffu, p3, 2);

            if ((t & 3) == 0) {
                sm.s.sev[(i0 + 0 * 256) >> 2] = p0;
                sm.s.sev[(i0 + 1 * 256) >> 2] = p1;
                sm.s.sev[(i0 + 2 * 256) >> 2] = p2;
                sm.s.sev[(i0 + 3 * 256) >> 2] = p3;
            }
        }
    }
    __syncthreads();

    // ===================== tail: ticket, gate, exp, rowsum ==================
    if (t == 0) sh_ticket = atomicAdd(&g_tick, 1u);
    __syncthreads();
    const unsigned ticket = sh_ticket;
    const unsigned gen = ticket / (unsigned)TOT;

    if (t == 0) spin_until_ge(&g_prod, (gen + 1u) * NPROD, 512);
    __syncthreads();

    {
        const int row = bid;
        const int b = row >> 10;
        const float si = ldcg(&g_si[row]);
        // batch the L2 loads (break the serial L2-latency chain)
        float sjv[4], sevv[4];
#pragma unroll
        for (int k = 0; k < 4; ++k) sjv[k] = ldcg(&g_sj[b * N_ + t + k * 256]);
#pragma unroll
        for (int k = 0; k < 4; ++k) sevv[k] = sm.s.sev[t + k * 256];
        float acc = 0.f;
#pragma unroll
        for (int k = 0; k < 4; ++k) {
            float s = si + sjv[k] + sevv[k];
            s = (s >= 0.f) ? s : 0.01f * s;            // leaky_relu
            acc += __expf(s);
        }
#pragma unroll
        for (int o = 16; o; o >>= 1) acc += __shfl_down_sync(0xffffffffu, acc, o);
        if (lane == 0) sm.s.red[w] = acc;
        __syncthreads();
        if (t == 0) {
            float s = 0.f;
#pragma unroll
            for (int k = 0; k < 8; ++k) s += sm.s.red[k];
            stcg(&g_rowsum[row], s);
            release_inc(&g_rdone);
        }
    }

    // ============== zout: last 128 tickets compute out slices ===============
    const unsigned slot = ticket - gen * (unsigned)TOT;   // 0..4095 this launch
    if (slot < (unsigned)(TOT - ZSLOTS)) return;
    const int zidx = (int)slot - (TOT - ZSLOTS);          // 0..127 fixed->rows
    const int row0 = zidx * ZROWS;

    if (t == 0) spin_until_ge(&g_rdone, (gen + 1u) * (unsigned)TOT, 256);
    __syncthreads();    // all threads gated; smem repurposed to .z

    {
        const int b = row0 >> 10;   // slice rows share one batch (32 | 1024)
        float a = 0.f;
#pragma unroll
        for (int k = t; k < N_; k += 256) a += ldcg(&g_rowsum[b * N_ + k]);
#pragma unroll
        for (int o = 16; o; o >>= 1) a += __shfl_down_sync(0xffffffffu, a, o);
        if (lane == 0) sm.z.red[w] = a;
        __syncthreads();
        if (t == 0) {
            float s = 0.f;
#pragma unroll
            for (int k = 0; k < 8; ++k) s += sm.z.red[k];
            sm.z.tot = s;
        }

#pragma unroll
        for (int idx = t; idx < H_ * D_; idx += 256) {
            const int d = idx >> 6, h = idx & 63;
            sm.z.wT[h * 65 + d] = w_fc[idx];
        }
#pragma unroll
        for (int idx = t; idx < ZROWS * H_; idx += 256)
            sm.z.h0s[idx] = __ldg(&h0[row0 * H_ + idx]);
        __syncthreads();

        const float inv = 1.0f / sm.z.tot;
        const int d = t & 63;
        const int rg = t >> 6;               // 0..3, 8 rows each
#pragma unroll
        for (int r8 = 0; r8 < 8; ++r8) {
            const int rl = rg * 8 + r8;
            const float* hr = &sm.z.h0s[rl * H_];
            float acc = 0.f;
#pragma unroll
            for (int h = 0; h < H_; ++h)
                acc = fmaf(hr[h], sm.z.wT[h * 65 + d], acc);
            const int row = row0 + rl;
            out[row * D_ + d] = ldcg(&g_rowsum[row]) * inv * acc;
        }
    }
}

// ---------------------------------------------------------------------------
extern "C" void kernel_launch(void* const* d_in, const int* in_sizes, int n_in,
                              void* d_out, int out_size) {
    const float* h0     = (const float*)d_in[0];   // (B,N,H)
    const float* e      = (const float*)d_in[1];   // (B,N,N,FE)
    const float* w_fc   = (const float*)d_in[2];   // (D,H)
    const float* w_attn = (const float*)d_in[3];   // (2D+FE,)
    float* out = (float*)d_out;                    // (B,N,D)

    k_all<<<TOT, 256>>>(h0, e, w_fc, w_attn, out);
}

// round 17
// speedup vs baseline: 1.4471x; 1.4471x over previous
#include <cuda_runtime.h>

// Problem constants
#define B_ 4
#define N_ 1024
#define H_ 64
#define D_ 64
#define FE_ 16
#define TOT (B_ * N_)

// Scratch (allocation-free: __device__ globals)
__device__ float g_si[TOT];
__device__ float g_sj[TOT];
__device__ float g_rowsum[TOT];

// PDL primitives
__device__ __forceinline__ void pdl_trigger() {
    asm volatile("griddepcontrol.launch_dependents;");
}
__device__ __forceinline__ void pdl_wait() {
    asm volatile("griddepcontrol.wait;" ::: "memory");
}

// ---------------------------------------------------------------------------
// k_sisj (R9 v3, measured 6.3us): sj[r]=h0[r,:]·u1, si[r]=h0[r,:]·u2,
// u = w_fc^T a. 256 blocks x 256 threads, 16 rows/block, 16 threads/row.
// Triggers dependents at start so k_row's grid launches/preambles under it.
// ---------------------------------------------------------------------------
__global__ void __launch_bounds__(256) k_sisj(const float* __restrict__ h0,
                                              const float* __restrict__ w_fc,
                                              const float* __restrict__ w_attn) {
    __shared__ __align__(16) float wfs[H_ * D_];    // 16 KB
    __shared__ __align__(16) float u1[H_];
    __shared__ __align__(16) float u2[H_];

    pdl_trigger();                 // k_row may launch; it gates on wait

    const int t = threadIdx.x;
    const int rl = t >> 4;                 // row within block: 0..15
    const int q  = t & 15;                 // float4 index within row
    const int row = blockIdx.x * 16 + rl;

    const float4 hv = __ldg(&reinterpret_cast<const float4*>(h0)[row * 16 + q]);

    const float4* w4 = reinterpret_cast<const float4*>(w_fc);
    float4* ws4 = reinterpret_cast<float4*>(wfs);
#pragma unroll
    for (int k = 0; k < 4; ++k) ws4[k * 256 + t] = w4[k * 256 + t];
    __syncthreads();

    if (t < 128) {
        const int h = t & 63;
        const float* a = w_attn + (t >> 6) * D_;    // a1 (t<64) or a2
        const float* col = wfs + h;
        float acc = 0.f;
#pragma unroll
        for (int d = 0; d < D_; ++d)
            acc = fmaf(col[d * H_], __ldg(&a[d]), acc);
        if (t < 64) u1[h] = acc; else u2[h] = acc;
    }
    __syncthreads();

    const float4 w1 = reinterpret_cast<const float4*>(u1)[q];
    const float4 w2 = reinterpret_cast<const float4*>(u2)[q];
    float s1 = hv.x * w1.x, s2 = hv.x * w2.x;
    s1 = fmaf(hv.y, w1.y, s1); s2 = fmaf(hv.y, w2.y, s2);
    s1 = fmaf(hv.z, w1.z, s1); s2 = fmaf(hv.z, w2.z, s2);
    s1 = fmaf(hv.w, w1.w, s1); s2 = fmaf(hv.w, w2.w, s2);
#pragma unroll
    for (int o = 8; o; o >>= 1) {
        s1 += __shfl_down_sync(0xffffffffu, s1, o, 16);
        s2 += __shfl_down_sync(0xffffffffu, s2, o, 16);
    }
    if (q == 0) {
        g_sj[row] = s1;
        g_si[row] = s2;
    }
}

// ---------------------------------------------------------------------------
// k_row (R7 proven body + PDL): one block per row, streams 64KB of e with
// lane-contiguous float4 loads; 4-lane shfl completes the 16-feature dot;
// exp 4x redundant, scaled 0.25. PDL: triggers k_zout at start; prefetches
// the first 2 e-float4s before griddepcontrol.wait (e needs no upstream).
// ---------------------------------------------------------------------------
__global__ void __launch_bounds__(256) k_row(const float* __restrict__ e,
                                             const float* __restrict__ w_attn) {
    __shared__ float sjs[N_];
    __shared__ float red[8];

    pdl_trigger();                 // k_zout may launch; it gates on wait

    const int row = blockIdx.x;    // b*N + i
    const int b = row >> 10;
    const int t = threadIdx.x;
    const int lane = t & 31;
    const int w = t >> 5;

    const int fg = (lane & 3) * 4;
    const float af0 = __ldg(&w_attn[2 * D_ + fg + 0]);
    const float af1 = __ldg(&w_attn[2 * D_ + fg + 1]);
    const float af2 = __ldg(&w_attn[2 * D_ + fg + 2]);
    const float af3 = __ldg(&w_attn[2 * D_ + fg + 3]);
    const float4* e4 = reinterpret_cast<const float4*>(e) + (size_t)row * (N_ * 4);

    // prefetch before the dependency wait (e is an input, not upstream data)
    const float4 pf0 = __ldcs(&e4[t]);
    const float4 pf1 = __ldcs(&e4[t + 256]);

    pdl_wait();                    // k_sisj complete; g_si/g_sj visible

#pragma unroll
    for (int j = t; j < N_; j += 256) sjs[j] = g_sj[b * N_ + j];
    __syncthreads();
    const float si = g_si[row];

    float acc = 0.f;
    auto proc = [&](const float4& v, int idx4) {
        float p = v.x * af0;
        p = fmaf(v.y, af1, p);
        p = fmaf(v.z, af2, p);
        p = fmaf(v.w, af3, p);
        p += __shfl_xor_sync(0xffffffffu, p, 1);
        p += __shfl_xor_sync(0xffffffffu, p, 2);
        float s = si + sjs[idx4 >> 2] + p;
        s = (s >= 0.f) ? s : 0.01f * s;              // leaky_relu
        acc += __expf(s);
    };
    proc(pf0, t);
    proc(pf1, t + 256);
#pragma unroll 7
    for (int idx4 = t + 512; idx4 < N_ * 4; idx4 += 256)
        proc(__ldcs(&e4[idx4]), idx4);

#pragma unroll
    for (int o = 16; o; o >>= 1) acc += __shfl_down_sync(0xffffffffu, acc, o);
    if (lane == 0) red[w] = acc;
    __syncthreads();
    if (t == 0) {
        float s = 0.f;
#pragma unroll
        for (int k = 0; k < 8; ++k) s += red[k];
        g_rowsum[row] = 0.25f * s;
    }
}

// ---------------------------------------------------------------------------
// k_zout (+PDL reorder): 128 blocks x 512 threads, 32 rows/block.
// PRE-wait (overlaps k_row's tail): stage wT + h0, compute the full z-GEMM
// into registers. POST-wait: batch totals from g_rowsum, scale, store.
// ---------------------------------------------------------------------------
#define RPB 32
#define WPITCH 65
__global__ void __launch_bounds__(512) k_zout(const float* __restrict__ h0,
                                              const float* __restrict__ w_fc,
                                              float* __restrict__ out) {
    __shared__ float wT[H_ * WPITCH];
    __shared__ __align__(16) float h0s[RPB * H_];
    __shared__ float red[16];
    __shared__ float rs_rows[RPB];
    __shared__ float s_total;

    const int t = threadIdx.x;
    const int row0 = blockIdx.x * RPB;
    const int b = blockIdx.x >> 5;                   // 32 blocks per batch

    // ---------- pre-wait: everything independent of g_rowsum ----------
#pragma unroll
    for (int idx = t; idx < H_ * D_; idx += 512) {
        const int d = idx >> 6, h = idx & 63;
        wT[h * WPITCH + d] = w_fc[idx];
    }
#pragma unroll
    for (int idx = t; idx < RPB * H_; idx += 512)
        h0s[idx] = h0[row0 * H_ + idx];
    __syncthreads();

    const int d  = t & 63;
    const int rg = t >> 6;                 // 0..7, 4 rows each
    const float4* h0v = reinterpret_cast<const float4*>(h0s);
    const int rbase = rg * 4;

    float acc0 = 0.f, acc1 = 0.f, acc2 = 0.f, acc3 = 0.f;
#pragma unroll
    for (int h4 = 0; h4 < H_ / 4; ++h4) {
        const float4 a0 = h0v[(rbase + 0) * (H_ / 4) + h4];
        const float4 a1 = h0v[(rbase + 1) * (H_ / 4) + h4];
        const float4 a2 = h0v[(rbase + 2) * (H_ / 4) + h4];
        const float4 a3 = h0v[(rbase + 3) * (H_ / 4) + h4];
        const float w0 = wT[(h4 * 4 + 0) * WPITCH + d];
        const float w1 = wT[(h4 * 4 + 1) * WPITCH + d];
        const float w2 = wT[(h4 * 4 + 2) * WPITCH + d];
        const float w3 = wT[(h4 * 4 + 3) * WPITCH + d];
        acc0 = fmaf(a0.x, w0, acc0); acc1 = fmaf(a1.x, w0, acc1);
        acc2 = fmaf(a2.x, w0, acc2); acc3 = fmaf(a3.x, w0, acc3);
        acc0 = fmaf(a0.y, w1, acc0); acc1 = fmaf(a1.y, w1, acc1);
        acc2 = fmaf(a2.y, w1, acc2); acc3 = fmaf(a3.y, w1, acc3);
        acc0 = fmaf(a0.z, w2, acc0); acc1 = fmaf(a1.z, w2, acc1);
        acc2 = fmaf(a2.z, w2, acc2); acc3 = fmaf(a3.z, w2, acc3);
        acc0 = fmaf(a0.w, w3, acc0); acc1 = fmaf(a1.w, w3, acc1);
        acc2 = fmaf(a2.w, w3, acc2); acc3 = fmaf(a3.w, w3, acc3);
    }

    // ---------- wait: k_row complete; g_rowsum visible ----------
    pdl_wait();

    {
        float a = g_rowsum[b * N_ + t] + g_rowsum[b * N_ + t + 512];
#pragma unroll
        for (int o = 16; o; o >>= 1) a += __shfl_down_sync(0xffffffffu, a, o);
        if ((t & 31) == 0) red[t >> 5] = a;
    }
    if (t < RPB) rs_rows[t] = g_rowsum[row0 + t];
    __syncthreads();
    if (t == 0) {
        float s = 0.f;
#pragma unroll
        for (int k = 0; k < 16; ++k) s += red[k];
        s_total = s;
    }
    __syncthreads();

    const float inv = 1.0f / s_total;
    const int r = row0 + rbase;
    out[(r + 0) * D_ + d] = rs_rows[rbase + 0] * inv * acc0;
    out[(r + 1) * D_ + d] = rs_rows[rbase + 1] * inv * acc1;
    out[(r + 2) * D_ + d] = rs_rows[rbase + 2] * inv * acc2;
    out[(r + 3) * D_ + d] = rs_rows[rbase + 3] * inv * acc3;
}

// ---------------------------------------------------------------------------
extern "C" void kernel_launch(void* const* d_in, const int* in_sizes, int n_in,
                              void* d_out, int out_size) {
    const float* h0     = (const float*)d_in[0];   // (B,N,H)
    const float* e      = (const float*)d_in[1];   // (B,N,N,FE)
    const float* w_fc   = (const float*)d_in[2];   // (D,H)
    const float* w_attn = (const float*)d_in[3];   // (2D+FE,)
    float* out = (float*)d_out;                    // (B,N,D)

    k_sisj<<<TOT / 16, 256>>>(h0, w_fc, w_attn);

    cudaLaunchAttribute attrs[1];
    attrs[0].id = cudaLaunchAttributeProgrammaticStreamSerialization;
    attrs[0].val.programmaticStreamSerializationAllowed = 1;

    cudaLaunchConfig_t cfg = {};
    cfg.stream = 0;
    cfg.attrs = attrs;
    cfg.numAttrs = 1;

    cfg.gridDim = dim3(TOT);
    cfg.blockDim = dim3(256);
    cudaLaunchKernelEx(&cfg, k_row, e, w_attn);

    cfg.gridDim = dim3(TOT / RPB);
    cfg.blockDim = dim3(512);
    cudaLaunchKernelEx(&cfg, k_zout, h0, w_fc, out);
}